// round 5
// baseline (speedup 1.0000x reference)
#include <cuda_runtime.h>
#include <cuda_fp16.h>
#include <cstdint>
#include <math.h>

#define T_TOK 512
#define DDIM  1024
#define FDIM  4096
#define NEXP  8
#define RNK   16
#define TOPK  2
#define LSCALE 2.0f
#define EPS   1e-6f

// ---------------- scratch (device globals; no allocation allowed) ----------
__device__ float g_t[T_TOK * DDIM];                 // normalized tokens
__device__ float g_base1[T_TOK * FDIM];             // t @ w1^T
__device__ float g_base3[T_TOK * FDIM];             // t @ w3^T
__device__ int   g_idx[T_TOK * TOPK];
__device__ float g_wgt[T_TOK * TOPK];
__device__ float g_act[T_TOK * TOPK * FDIM];        // silu(h1)*h3
__device__ float g_lr2[T_TOK * TOPK * RNK];
__device__ float g_y[T_TOK * TOPK * DDIM];          // act @ w2^T
__device__ int   g_cnt[NEXP];
__device__ int   g_lst[NEXP * T_TOK];
__device__ float g_apk[256 * DDIM];                 // packed [a1(8x16); a3(8x16)] rows
__device__ float g_lrall[T_TOK * 256];              // t @ apk^T (unscaled)

// ---------------- helpers ---------------------------------------------------
__device__ __forceinline__ uint32_t pack2(float lo, float hi) {
    __half2 h = __floats2half2_rn(lo, hi);   // .x = lo (low 16 bits)
    return *reinterpret_cast<uint32_t*>(&h);
}
__device__ __forceinline__ void mma_f16(float* c, const uint32_t* a, const uint32_t* b) {
    asm volatile(
        "mma.sync.aligned.m16n8k16.row.col.f32.f16.f16.f32 "
        "{%0,%1,%2,%3}, {%4,%5,%6,%7}, {%8,%9}, {%0,%1,%2,%3};"
        : "+f"(c[0]), "+f"(c[1]), "+f"(c[2]), "+f"(c[3])
        : "r"(a[0]), "r"(a[1]), "r"(a[2]), "r"(a[3]), "r"(b[0]), "r"(b[1]));
}

// ---------------- fast all-FMA silu (no MUFU) -------------------------------
__device__ __forceinline__ float fast_silu(float x) {
    float u = -x * 1.442695041f;
    float rn = u + 12582912.f;
    float n = rn - 12582912.f;
    float f = u - n;
    float p = 1.3333558146e-3f;
    p = fmaf(p, f, 9.6181291077e-3f);
    p = fmaf(p, f, 5.5504108664e-2f);
    p = fmaf(p, f, 2.4022650696e-1f);
    p = fmaf(p, f, 6.9314718056e-1f);
    p = fmaf(p, f, 1.0f);
    int ei = __float2int_rn(n);
    ei = ei > 60 ? 60 : (ei < -126 ? -126 : ei);
    float s = __int_as_float((ei + 127) << 23);
    float y = p * s;
    float d = 1.0f + y;
    float r = __int_as_float(0x7EF311C4 - __float_as_int(d));
    r = r * fmaf(-d, r, 2.0f);
    r = r * fmaf(-d, r, 2.0f);
    r = r * fmaf(-d, r, 2.0f);
    return x * r;
}

// ---------------- K1: RMSNorm ----------------------------------------------
__global__ void k_rmsnorm(const float* __restrict__ x, const float* __restrict__ nw) {
    int t = blockIdx.x;
    const float* xr = x + t * DDIM;
    float ss = 0.f;
    for (int i = threadIdx.x; i < DDIM; i += blockDim.x) {
        float v = xr[i];
        ss += v * v;
    }
    __shared__ float sred[32];
    for (int o = 16; o; o >>= 1) ss += __shfl_xor_sync(0xffffffffu, ss, o);
    if ((threadIdx.x & 31) == 0) sred[threadIdx.x >> 5] = ss;
    __syncthreads();
    if (threadIdx.x < 32) {
        float v = (threadIdx.x < (blockDim.x >> 5)) ? sred[threadIdx.x] : 0.f;
        for (int o = 16; o; o >>= 1) v += __shfl_xor_sync(0xffffffffu, v, o);
        if (threadIdx.x == 0) sred[0] = v;
    }
    __syncthreads();
    float scale = rsqrtf(sred[0] / (float)DDIM + EPS);
    for (int i = threadIdx.x; i < DDIM; i += blockDim.x)
        g_t[t * DDIM + i] = xr[i] * scale * nw[i];
}

// ---------------- K2: router ------------------------------------------------
__global__ void k_router(const float* __restrict__ gw) {
    int t = blockIdx.x;
    int w = threadIdx.x >> 5, l = threadIdx.x & 31;
    const float* tr = g_t + t * DDIM;
    const float* gr = gw + w * DDIM;
    float s = 0.f;
    for (int i = l; i < DDIM; i += 32) s += tr[i] * gr[i];
    for (int o = 16; o; o >>= 1) s += __shfl_xor_sync(0xffffffffu, s, o);
    __shared__ float logits[NEXP];
    if (l == 0) logits[w] = s;
    __syncthreads();
    if (threadIdx.x == 0) {
        float mx = logits[0];
        for (int e = 1; e < NEXP; e++) mx = fmaxf(mx, logits[e]);
        float p[NEXP], sum = 0.f;
        for (int e = 0; e < NEXP; e++) { p[e] = expf(logits[e] - mx); sum += p[e]; }
        for (int e = 0; e < NEXP; e++) p[e] /= sum;
        int i0 = 0;
        for (int e = 1; e < NEXP; e++) if (p[e] > p[i0]) i0 = e;
        int i1 = -1;
        for (int e = 0; e < NEXP; e++) {
            if (e == i0) continue;
            if (i1 < 0 || p[e] > p[i1]) i1 = e;
        }
        float w0 = p[i0], w1 = p[i1], tw = w0 + w1;
        g_idx[t * 2 + 0] = i0;  g_idx[t * 2 + 1] = i1;
        g_wgt[t * 2 + 0] = w0 / tw;  g_wgt[t * 2 + 1] = w1 / tw;
    }
}

// ---------------- K2b: per-expert row lists ---------------------------------
__global__ void k_build() {
    int tid = threadIdx.x;
    if (tid < NEXP) g_cnt[tid] = 0;
    __syncthreads();
    int e = g_idx[tid];
    int pos = atomicAdd(&g_cnt[e], 1);
    g_lst[e * T_TOK + pos] = tid;
}

// ============================================================================
// fp16 m16n8k16 NT GEMM: C[M,N] = A[M,K] @ B[N,K]^T, fp32 in/out.
// BK=32, 256 threads (8 warps). BM=128: warp tile 32x64 (warps 4x2, NT=8).
// BM=64: warp tile 32x32 (warps 2x4, NT=4). Per-thread full-row 128B loads,
// fp32->fp16x2 pack at STS. smem row stride 20 u32 (conflict-free for both
// fragment LDS and STS.128). Double buffer, 1 sync/iter, reg prefetch.
// Optional second B/C (column-fused launch): blocks with blockIdx.x >= nbx
// use (B2, C2).
// ============================================================================
template<int BM>
__global__ void __launch_bounds__(256)
k_hgemm(int M, int N, int K,
        const float* __restrict__ A, const float* __restrict__ B0,
        float* __restrict__ C0,
        const float* __restrict__ B2, float* __restrict__ C2, int nbx) {
    constexpr int BN = 128;
    constexpr int WM = BM / 32;          // warps along M
    constexpr int WN = 8 / WM;           // warps along N
    constexpr int NT = BN / (8 * WN);    // n-tiles per warp
    constexpr int NROW = BM + BN;
    constexpr int SSTG = NROW * 20;      // u32 per stage

    extern __shared__ uint32_t sm[];
    int tid = threadIdx.x;
    int wid = tid >> 5, lane = tid & 31;
    int qr = lane >> 2, qc = lane & 3;
    int wm = wid % WM, wn = wid / WM;

    int bx = blockIdx.x;
    const float* B = B0;
    float* C = C0;
    if (B2 != nullptr && bx >= nbx) { B = B2; C = C2; bx -= nbx; }
    int bm = blockIdx.y * BM, bn = bx * BN;

    bool active = tid < NROW;
    const float4* gsrc = nullptr;
    if (active) {
        const float* base = (tid < BM) ? (A + (size_t)(bm + tid) * K)
                                       : (B + (size_t)(bn + tid - BM) * K);
        gsrc = (const float4*)base;
    }
    uint32_t srow = (uint32_t)tid * 20u;

    float4 pf[8];
    if (active) {
#pragma unroll
        for (int q = 0; q < 8; q++) pf[q] = gsrc[q];
    }

    float acc[2][NT][4];
#pragma unroll
    for (int i = 0; i < 2; i++)
#pragma unroll
        for (int j = 0; j < NT; j++)
#pragma unroll
            for (int q = 0; q < 4; q++) acc[i][j][q] = 0.f;

    int niter = K >> 5;
    for (int it = 0; it < niter; ++it) {
        uint32_t* st = sm + (it & 1) * SSTG;
        if (active) {
#pragma unroll
            for (int q = 0; q < 4; q++) {
                float4 v0 = pf[2 * q], v1 = pf[2 * q + 1];
                uint4 w = make_uint4(pack2(v0.x, v0.y), pack2(v0.z, v0.w),
                                     pack2(v1.x, v1.y), pack2(v1.z, v1.w));
                *(uint4*)(st + srow + q * 4) = w;    // STS.128
            }
        }
        __syncthreads();
        if (it + 1 < niter && active) {
            gsrc += 8;
#pragma unroll
            for (int q = 0; q < 8; q++) pf[q] = gsrc[q];
        }
#pragma unroll
        for (int g = 0; g < 2; ++g) {
            uint32_t af[2][4], bf[NT][2];
#pragma unroll
            for (int mt = 0; mt < 2; mt++) {
                uint32_t r0 = (uint32_t)(wm * 32 + mt * 16 + qr) * 20u + g * 8 + qc;
                af[mt][0] = st[r0];
                af[mt][1] = st[r0 + 8 * 20];
                af[mt][2] = st[r0 + 4];
                af[mt][3] = st[r0 + 8 * 20 + 4];
            }
#pragma unroll
            for (int nt = 0; nt < NT; nt++) {
                uint32_t r0 = (uint32_t)(BM + wn * (NT * 8) + nt * 8 + qr) * 20u
                            + g * 8 + qc;
                bf[nt][0] = st[r0];
                bf[nt][1] = st[r0 + 4];
            }
#pragma unroll
            for (int mt = 0; mt < 2; mt++)
#pragma unroll
                for (int nt = 0; nt < NT; nt++)
                    mma_f16(acc[mt][nt], af[mt], bf[nt]);
        }
        __syncthreads();
    }

#pragma unroll
    for (int mt = 0; mt < 2; mt++)
#pragma unroll
        for (int nt = 0; nt < NT; nt++) {
            int row0 = bm + wm * 32 + mt * 16 + qr;
            int col  = bn + wn * (NT * 8) + nt * 8 + 2 * qc;
            *(float2*)&C[(size_t)row0 * N + col] =
                make_float2(acc[mt][nt][0], acc[mt][nt][1]);
            *(float2*)&C[(size_t)(row0 + 8) * N + col] =
                make_float2(acc[mt][nt][2], acc[mt][nt][3]);
        }
}

// ---------------- K5: expert-grouped LoRA-B + SwiGLU ------------------------
__global__ void __launch_bounds__(512)
k_act2(const float* __restrict__ b1, const float* __restrict__ b3) {
    int e = blockIdx.x;
    int f = blockIdx.y * 512 + threadIdx.x;
    float br1[RNK], br3[RNK];
    const float4* p1 = (const float4*)(b1 + ((size_t)e * FDIM + f) * RNK);
    const float4* p3 = (const float4*)(b3 + ((size_t)e * FDIM + f) * RNK);
#pragma unroll
    for (int q = 0; q < 4; q++) {
        float4 v = p1[q];
        br1[q*4+0] = v.x; br1[q*4+1] = v.y; br1[q*4+2] = v.z; br1[q*4+3] = v.w;
        v = p3[q];
        br3[q*4+0] = v.x; br3[q*4+1] = v.y; br3[q*4+2] = v.z; br3[q*4+3] = v.w;
    }
    int n = g_cnt[e];
    __shared__ float s1[16][RNK], s3[16][RNK];
    __shared__ int sr[16];
    for (int i0 = 0; i0 < n; i0 += 16) {
        int batch = min(16, n - i0);
        __syncthreads();
        int q = threadIdx.x;
        int j = q >> 5, v = q & 31;
        if (j < batch) {
            int row = g_lst[e * T_TOK + i0 + j];
            int t = row >> 1;
            if (v == 0) sr[j] = row;
            if (v < RNK) s1[j][v] = LSCALE * g_lrall[t * 256 + e * RNK + v];
            else         s3[j][v - RNK] = LSCALE * g_lrall[t * 256 + 128 + e * RNK + (v - RNK)];
        }
        __syncthreads();
        for (int jj = 0; jj < batch; jj++) {
            int row = sr[jj];
            int t = row >> 1;
            float h1 = __ldg(&g_base1[(size_t)t * FDIM + f]);
            float h3 = __ldg(&g_base3[(size_t)t * FDIM + f]);
#pragma unroll
            for (int r = 0; r < RNK; r++) {
                h1 = fmaf(s1[jj][r], br1[r], h1);
                h3 = fmaf(s3[jj][r], br3[r], h3);
            }
            g_act[(size_t)row * FDIM + f] = fast_silu(h1) * h3;
        }
    }
}

// ---------------- K6: expert-grouped LoRA-A down projection -----------------
#define L2FC 512
#define L2ST 516
__global__ void __launch_bounds__(256)
k_lora2g(const float* __restrict__ a2) {
    extern __shared__ float smf[];
    float* s_act = smf;
    float* s_a2  = smf + 32 * L2ST;
    int e = blockIdx.x, rb = blockIdx.y;
    int n = g_cnt[e];
    int r0 = rb * 32;
    if (r0 >= n) return;
    int nrows = min(32, n - r0);
    int tid = threadIdx.x;
    __shared__ int s_row[32];
    if (tid < 32) s_row[tid] = (tid < nrows) ? g_lst[e * T_TOK + r0 + tid] : -1;
    __syncthreads();
    int myrow = tid >> 3;
    int rp = (tid & 7) * 2;
    float acc0 = 0.f, acc1 = 0.f;
    for (int f0 = 0; f0 < FDIM; f0 += L2FC) {
        for (int q = tid; q < 32 * 128; q += 256) {
            int j = q >> 7, c4 = q & 127;
            float4 v = make_float4(0.f, 0.f, 0.f, 0.f);
            int row = s_row[j];
            if (row >= 0) v = *(const float4*)(g_act + (size_t)row * FDIM + f0 + c4 * 4);
            float* d = s_act + j * L2ST + c4 * 4;
            d[0] = v.x; d[1] = v.y; d[2] = v.z; d[3] = v.w;
        }
        for (int q = tid; q < 16 * 128; q += 256) {
            int j = q >> 7, c4 = q & 127;
            float4 v = *(const float4*)(a2 + ((size_t)e * RNK + j) * FDIM + f0 + c4 * 4);
            float* d = s_a2 + j * L2ST + c4 * 4;
            d[0] = v.x; d[1] = v.y; d[2] = v.z; d[3] = v.w;
        }
        __syncthreads();
        const float* ar0 = s_a2 + rp * L2ST;
        const float* ar1 = s_a2 + (rp + 1) * L2ST;
        const float* ac = s_act + myrow * L2ST;
#pragma unroll 8
        for (int f = 0; f < L2FC; f++) {
            float a = ac[f];
            acc0 = fmaf(a, ar0[f], acc0);
            acc1 = fmaf(a, ar1[f], acc1);
        }
        __syncthreads();
    }
    if (myrow < nrows) {
        int row = s_row[myrow];
        g_lr2[row * RNK + rp]     = LSCALE * acc0;
        g_lr2[row * RNK + rp + 1] = LSCALE * acc1;
    }
}

// ---------------- K8: LoRA-B down + expert mix ------------------------------
__global__ void k_mix(const float* __restrict__ b2, float* __restrict__ out) {
    int t = blockIdx.x;
    __shared__ float l2[TOPK][RNK];
    __shared__ int   se[TOPK];
    __shared__ float sw[TOPK];
    if (threadIdx.x < TOPK * RNK) {
        int k = threadIdx.x / RNK, r = threadIdx.x % RNK;
        l2[k][r] = g_lr2[(t * TOPK + k) * RNK + r];
    }
    if (threadIdx.x < TOPK) {
        se[threadIdx.x] = g_idx[t * TOPK + threadIdx.x];
        sw[threadIdx.x] = g_wgt[t * TOPK + threadIdx.x];
    }
    __syncthreads();
    for (int d = threadIdx.x; d < DDIM; d += blockDim.x) {
        float o = 0.f;
#pragma unroll
        for (int k = 0; k < TOPK; k++) {
            int row = t * TOPK + k;
            float v = g_y[(size_t)row * DDIM + d];
            const float4* br = (const float4*)(b2 + ((size_t)se[k] * DDIM + d) * RNK);
#pragma unroll
            for (int q = 0; q < 4; q++) {
                float4 b = br[q];
                v += l2[k][q*4+0]*b.x + l2[k][q*4+1]*b.y + l2[k][q*4+2]*b.z + l2[k][q*4+3]*b.w;
            }
            o += sw[k] * v;
        }
        out[t * DDIM + d] = o;
    }
}

// ---------------- launch ----------------------------------------------------
extern "C" void kernel_launch(void* const* d_in, const int* in_sizes, int n_in,
                              void* d_out, int out_size) {
    const float* x      = (const float*)d_in[0];
    const float* norm_w = (const float*)d_in[1];
    const float* w1     = (const float*)d_in[2];
    const float* w3     = (const float*)d_in[3];
    const float* w2     = (const float*)d_in[4];
    const float* gate_w = (const float*)d_in[5];
    const float* a1     = (const float*)d_in[6];
    const float* b1     = (const float*)d_in[7];
    const float* a3     = (const float*)d_in[8];
    const float* b3     = (const float*)d_in[9];
    const float* a2     = (const float*)d_in[10];
    const float* b2     = (const float*)d_in[11];
    float* out = (float*)d_out;

    float* t_ptr;   cudaGetSymbolAddress((void**)&t_ptr,   g_t);
    float* base1;   cudaGetSymbolAddress((void**)&base1,   g_base1);
    float* base3;   cudaGetSymbolAddress((void**)&base3,   g_base3);
    float* act_ptr; cudaGetSymbolAddress((void**)&act_ptr, g_act);
    float* y_ptr;   cudaGetSymbolAddress((void**)&y_ptr,   g_y);
    float* apk;     cudaGetSymbolAddress((void**)&apk,     g_apk);
    float* lrall;   cudaGetSymbolAddress((void**)&lrall,   g_lrall);

    static int attr_set = 0;
    if (!attr_set) {
        cudaFuncSetAttribute(k_lora2g, cudaFuncAttributeMaxDynamicSharedMemorySize,
                             48 * L2ST * 4);
        attr_set = 1;
    }

    const int SM128 = (128 + 128) * 20 * 4 * 2;   // 40960 B
    const int SM64  = (64 + 128) * 20 * 4 * 2;    // 30720 B

    // pack [a1; a3] -> g_apk rows (row-contiguous layouts)
    cudaMemcpyAsync(apk, a1, (size_t)NEXP * RNK * DDIM * sizeof(float),
                    cudaMemcpyDeviceToDevice);
    cudaMemcpyAsync(apk + NEXP * RNK * DDIM, a3,
                    (size_t)NEXP * RNK * DDIM * sizeof(float),
                    cudaMemcpyDeviceToDevice);

    k_rmsnorm<<<T_TOK, 256>>>(x, norm_w);
    k_router<<<T_TOK, 256>>>(gate_w);
    k_build<<<1, T_TOK * TOPK>>>();

    // LoRA-A up projections for all experts as one GEMM: [512, 256]
    k_hgemm<64><<<dim3(2, 8), 256, SM64>>>(T_TOK, 256, DDIM,
                                           t_ptr, apk, lrall, nullptr, nullptr, 0);

    // fused base up projections (w1 | w3 share A): 64 x 4 grid
    k_hgemm<128><<<dim3(64, 4), 256, SM128>>>(T_TOK, FDIM, DDIM,
                                              t_ptr, w1, base1, w3, base3, 32);

    k_act2<<<dim3(NEXP, FDIM / 512), 512>>>(b1, b3);
    k_lora2g<<<dim3(NEXP, 16), 256, 48 * L2ST * 4>>>(a2);

    // down projection: [1024, 1024] = act @ w2^T
    k_hgemm<64><<<dim3(8, 16), 256, SM64>>>(T_TOK * TOPK, DDIM, FDIM,
                                            act_ptr, w2, y_ptr, nullptr, nullptr, 0);

    k_mix<<<T_TOK, 256>>>(b2, out);
}

// round 6
// speedup vs baseline: 1.5287x; 1.5287x over previous
#include <cuda_runtime.h>
#include <cuda_fp16.h>
#include <cstdint>
#include <math.h>

#define T_TOK 512
#define DDIM  1024
#define FDIM  4096
#define NEXP  8
#define RNK   16
#define TOPK  2
#define LSCALE 2.0f
#define EPS   1e-6f

// ---------------- scratch (device globals; no allocation allowed) ----------
__device__ float  g_t[T_TOK * DDIM];
__device__ __half g_th[T_TOK * DDIM];
__device__ float  g_base1[T_TOK * FDIM];
__device__ float  g_base3[T_TOK * FDIM];
__device__ int    g_idx[T_TOK * TOPK];
__device__ float  g_wgt[T_TOK * TOPK];
__device__ float  g_act[T_TOK * TOPK * FDIM];
__device__ __half g_acth[T_TOK * TOPK * FDIM];
__device__ float  g_lr2[T_TOK * TOPK * RNK];
__device__ float  g_y[T_TOK * TOPK * DDIM];
__device__ float  g_y2[T_TOK * TOPK * DDIM];
__device__ int    g_cnt[NEXP];
__device__ int    g_lst[NEXP * T_TOK];
__device__ __half g_w1h[FDIM * DDIM];
__device__ __half g_w3h[FDIM * DDIM];
__device__ __half g_w2h[DDIM * FDIM];
__device__ __half g_apkh[256 * DDIM];               // [a1 rows(128); a3 rows(128)]
__device__ float  g_lrall[T_TOK * 256];             // t @ apk^T (unscaled)

// ---------------- helpers ---------------------------------------------------
__device__ __forceinline__ uint32_t smem_to_u32(const void* p) {
    uint32_t a;
    asm("{ .reg .u64 t; cvta.to.shared.u64 t, %1; cvt.u32.u64 %0, t; }" : "=r"(a) : "l"(p));
    return a;
}
__device__ __forceinline__ uint32_t pack2(float lo, float hi) {
    __half2 h = __floats2half2_rn(lo, hi);
    return *reinterpret_cast<uint32_t*>(&h);
}
__device__ __forceinline__ void mma_f16(float* c, const uint32_t* a, const uint32_t* b) {
    asm volatile(
        "mma.sync.aligned.m16n8k16.row.col.f32.f16.f16.f32 "
        "{%0,%1,%2,%3}, {%4,%5,%6,%7}, {%8,%9}, {%0,%1,%2,%3};"
        : "+f"(c[0]), "+f"(c[1]), "+f"(c[2]), "+f"(c[3])
        : "r"(a[0]), "r"(a[1]), "r"(a[2]), "r"(a[3]), "r"(b[0]), "r"(b[1]));
}
#define CP_ASYNC16(dst, src) \
    asm volatile("cp.async.cg.shared.global [%0], [%1], 16;" :: "r"(dst), "l"(src))
#define CP_COMMIT() asm volatile("cp.async.commit_group;" ::: "memory")
#define CP_WAIT2()  asm volatile("cp.async.wait_group 2;" ::: "memory")

// ---------------- fast all-FMA silu (no MUFU) -------------------------------
__device__ __forceinline__ float fast_silu(float x) {
    float u = -x * 1.442695041f;
    float rn = u + 12582912.f;
    float n = rn - 12582912.f;
    float f = u - n;
    float p = 1.3333558146e-3f;
    p = fmaf(p, f, 9.6181291077e-3f);
    p = fmaf(p, f, 5.5504108664e-2f);
    p = fmaf(p, f, 2.4022650696e-1f);
    p = fmaf(p, f, 6.9314718056e-1f);
    p = fmaf(p, f, 1.0f);
    int ei = __float2int_rn(n);
    ei = ei > 60 ? 60 : (ei < -126 ? -126 : ei);
    float s = __int_as_float((ei + 127) << 23);
    float y = p * s;
    float d = 1.0f + y;
    float r = __int_as_float(0x7EF311C4 - __float_as_int(d));
    r = r * fmaf(-d, r, 2.0f);
    r = r * fmaf(-d, r, 2.0f);
    r = r * fmaf(-d, r, 2.0f);
    return x * r;
}

// ---------------- conversion kernels ----------------------------------------
__global__ void __launch_bounds__(256)
k_cvt_up(const float* __restrict__ w1, const float* __restrict__ w3) {
    const size_t n4 = (size_t)FDIM * DDIM / 4;
    size_t i = (size_t)blockIdx.x * 256 + threadIdx.x;
    float4 v;
    uint2* dst;
    if (i < n4) { v = ((const float4*)w1)[i]; dst = (uint2*)g_w1h + i; }
    else        { v = ((const float4*)w3)[i - n4]; dst = (uint2*)g_w3h + (i - n4); }
    *dst = make_uint2(pack2(v.x, v.y), pack2(v.z, v.w));
}
__global__ void __launch_bounds__(256)
k_cvt_rest(const float* __restrict__ w2, const float* __restrict__ a1,
           const float* __restrict__ a3) {
    const size_t n4w = (size_t)DDIM * FDIM / 4;          // 1M float4
    const size_t n4a = (size_t)NEXP * RNK * DDIM / 4;    // 32768 float4
    size_t i = (size_t)blockIdx.x * 256 + threadIdx.x;
    float4 v;
    uint2* dst;
    if (i < n4w) { v = ((const float4*)w2)[i]; dst = (uint2*)g_w2h + i; }
    else {
        size_t j = i - n4w;
        if (j < n4a) { v = ((const float4*)a1)[j]; dst = (uint2*)g_apkh + j; }
        else         { v = ((const float4*)a3)[j - n4a]; dst = (uint2*)g_apkh + (j - n4a) + n4a; }
    }
    *dst = make_uint2(pack2(v.x, v.y), pack2(v.z, v.w));
}

// ---------------- K1: RMSNorm (writes fp32 + fp16) --------------------------
__global__ void k_rmsnorm(const float* __restrict__ x, const float* __restrict__ nw) {
    int t = blockIdx.x;
    const float* xr = x + t * DDIM;
    float ss = 0.f;
    for (int i = threadIdx.x; i < DDIM; i += blockDim.x) {
        float v = xr[i];
        ss += v * v;
    }
    __shared__ float sred[32];
    for (int o = 16; o; o >>= 1) ss += __shfl_xor_sync(0xffffffffu, ss, o);
    if ((threadIdx.x & 31) == 0) sred[threadIdx.x >> 5] = ss;
    __syncthreads();
    if (threadIdx.x < 32) {
        float v = (threadIdx.x < (blockDim.x >> 5)) ? sred[threadIdx.x] : 0.f;
        for (int o = 16; o; o >>= 1) v += __shfl_xor_sync(0xffffffffu, v, o);
        if (threadIdx.x == 0) sred[0] = v;
    }
    __syncthreads();
    float scale = rsqrtf(sred[0] / (float)DDIM + EPS);
    for (int i = threadIdx.x; i < DDIM; i += blockDim.x) {
        float v = xr[i] * scale * nw[i];
        g_t[t * DDIM + i] = v;
        g_th[t * DDIM + i] = __float2half(v);
    }
}

// ---------------- K2: router ------------------------------------------------
__global__ void k_router(const float* __restrict__ gw) {
    int t = blockIdx.x;
    int w = threadIdx.x >> 5, l = threadIdx.x & 31;
    const float* tr = g_t + t * DDIM;
    const float* gr = gw + w * DDIM;
    float s = 0.f;
    for (int i = l; i < DDIM; i += 32) s += tr[i] * gr[i];
    for (int o = 16; o; o >>= 1) s += __shfl_xor_sync(0xffffffffu, s, o);
    __shared__ float logits[NEXP];
    if (l == 0) logits[w] = s;
    __syncthreads();
    if (threadIdx.x == 0) {
        float mx = logits[0];
        for (int e = 1; e < NEXP; e++) mx = fmaxf(mx, logits[e]);
        float p[NEXP], sum = 0.f;
        for (int e = 0; e < NEXP; e++) { p[e] = expf(logits[e] - mx); sum += p[e]; }
        for (int e = 0; e < NEXP; e++) p[e] /= sum;
        int i0 = 0;
        for (int e = 1; e < NEXP; e++) if (p[e] > p[i0]) i0 = e;
        int i1 = -1;
        for (int e = 0; e < NEXP; e++) {
            if (e == i0) continue;
            if (i1 < 0 || p[e] > p[i1]) i1 = e;
        }
        float w0 = p[i0], w1 = p[i1], tw = w0 + w1;
        g_idx[t * 2 + 0] = i0;  g_idx[t * 2 + 1] = i1;
        g_wgt[t * 2 + 0] = w0 / tw;  g_wgt[t * 2 + 1] = w1 / tw;
    }
}

// ---------------- K2b: per-expert row lists ---------------------------------
__global__ void k_build() {
    int tid = threadIdx.x;
    if (tid < NEXP) g_cnt[tid] = 0;
    __syncthreads();
    int e = g_idx[tid];
    int pos = atomicAdd(&g_cnt[e], 1);
    g_lst[e * T_TOK + pos] = tid;
}

// ============================================================================
// cp.async 4-stage fp16 GEMM core. Tile 128x128, BK=32 fp16 (64B/row).
// 256 threads, 8 warps (2 M x 4 N), warp tile 64x32 -> 4x4 m16n8k16 tiles.
// smem row stride 20 u32 (80B, conflict-free), stage = 256 rows = 20480B.
// One __syncthreads per K-iter; issue of stage it+3 after the barrier
// (buffer (it-1)%4, proven free by the barrier).
// ============================================================================
#define SSTG 5120   // u32 per stage
#define GSM  (4 * SSTG * 4)   // 81920 B

__device__ __forceinline__ void gemm_core(
    const __half* __restrict__ Arow, const __half* __restrict__ Brow,
    float* __restrict__ C, int N, int niter, int bm, int bn,
    uint32_t* sm, uint32_t smb) {
    int tid = threadIdx.x;
    int wid = tid >> 5, lane = tid & 31;
    int qr = lane >> 2, qc = lane & 3;
    int wm = wid & 1, wn = wid >> 1;

    const __half* gsrc = (tid < 128) ? Arow : Brow;   // caller pre-offsets rows
    uint32_t srow_b = smb + (uint32_t)tid * 80u;

    float acc[4][4][4];
#pragma unroll
    for (int i = 0; i < 4; i++)
#pragma unroll
        for (int j = 0; j < 4; j++)
#pragma unroll
            for (int q = 0; q < 4; q++) acc[i][j][q] = 0.f;

#pragma unroll
    for (int s = 0; s < 3; s++) {
        if (s < niter) {
            const __half* src = gsrc + s * 32;
            uint32_t d = srow_b + (uint32_t)s * 20480u;
#pragma unroll
            for (int c = 0; c < 4; c++) CP_ASYNC16(d + c * 16, src + c * 8);
        }
        CP_COMMIT();
    }

    for (int it = 0; it < niter; ++it) {
        CP_WAIT2();
        __syncthreads();
        int nx = it + 3;
        if (nx < niter) {
            const __half* src = gsrc + nx * 32;
            uint32_t d = srow_b + (uint32_t)(nx & 3) * 20480u;
#pragma unroll
            for (int c = 0; c < 4; c++) CP_ASYNC16(d + c * 16, src + c * 8);
        }
        CP_COMMIT();

        const uint32_t* st = sm + (it & 3) * SSTG;
#pragma unroll
        for (int g = 0; g < 2; ++g) {
            uint32_t af[4][4], bf[4][2];
#pragma unroll
            for (int mt = 0; mt < 4; mt++) {
                uint32_t r0 = (uint32_t)(wm * 64 + mt * 16 + qr) * 20u + g * 8 + qc;
                af[mt][0] = st[r0];
                af[mt][1] = st[r0 + 8 * 20];
                af[mt][2] = st[r0 + 4];
                af[mt][3] = st[r0 + 8 * 20 + 4];
            }
#pragma unroll
            for (int nt = 0; nt < 4; nt++) {
                uint32_t r0 = (uint32_t)(128 + wn * 32 + nt * 8 + qr) * 20u + g * 8 + qc;
                bf[nt][0] = st[r0];
                bf[nt][1] = st[r0 + 4];
            }
#pragma unroll
            for (int mt = 0; mt < 4; mt++)
#pragma unroll
                for (int nt = 0; nt < 4; nt++)
                    mma_f16(acc[mt][nt], af[mt], bf[nt]);
        }
    }

#pragma unroll
    for (int mt = 0; mt < 4; mt++)
#pragma unroll
        for (int nt = 0; nt < 4; nt++) {
            int row0 = bm + wm * 64 + mt * 16 + qr;
            int col  = bn + wn * 32 + nt * 8 + 2 * qc;
            *(float2*)&C[(size_t)row0 * N + col] =
                make_float2(acc[mt][nt][0], acc[mt][nt][1]);
            *(float2*)&C[(size_t)(row0 + 8) * N + col] =
                make_float2(acc[mt][nt][2], acc[mt][nt][3]);
        }
}

// fused up GEMM: A = g_th [512,1024]; segments w1 | w3 | apk
__global__ void __launch_bounds__(256)
k_up_gemm() {
    extern __shared__ uint32_t sm[];
    uint32_t smb = smem_to_u32(sm);
    int bx = blockIdx.x;
    int bm = blockIdx.y * 128;
    const __half* B;
    float* C;
    int N, bn;
    if (bx < 32)      { B = g_w1h; C = g_base1; N = FDIM; bn = bx * 128; }
    else if (bx < 64) { B = g_w3h; C = g_base3; N = FDIM; bn = (bx - 32) * 128; }
    else              { B = g_apkh; C = g_lrall; N = 256; bn = (bx - 64) * 128; }
    int tid = threadIdx.x;
    const __half* Arow = g_th + (size_t)(bm + tid) * DDIM;
    const __half* Brow = B + (size_t)(bn + (tid - 128)) * DDIM;
    gemm_core(Arow, Brow, C, N, DDIM / 32, bm, bn, sm, smb);
}

// down GEMM, split-K x2: A = g_acth [1024,4096], B = g_w2h [1024,4096]
__global__ void __launch_bounds__(256)
k_dn_gemm() {
    extern __shared__ uint32_t sm[];
    uint32_t smb = smem_to_u32(sm);
    int bm = blockIdx.y * 128, bn = blockIdx.x * 128;
    int kz = blockIdx.z;
    int kOff = kz * (FDIM / 2);
    float* C = kz ? g_y2 : g_y;
    int tid = threadIdx.x;
    const __half* Arow = g_acth + (size_t)(bm + tid) * FDIM + kOff;
    const __half* Brow = g_w2h + (size_t)(bn + (tid - 128)) * FDIM + kOff;
    gemm_core(Arow, Brow, C, DDIM, (FDIM / 2) / 32, bm, bn, sm, smb);
}

// ---------------- K5: expert-grouped LoRA-B + SwiGLU ------------------------
__global__ void __launch_bounds__(512)
k_act2(const float* __restrict__ b1, const float* __restrict__ b3) {
    int e = blockIdx.x;
    int f = blockIdx.y * 512 + threadIdx.x;
    float br1[RNK], br3[RNK];
    const float4* p1 = (const float4*)(b1 + ((size_t)e * FDIM + f) * RNK);
    const float4* p3 = (const float4*)(b3 + ((size_t)e * FDIM + f) * RNK);
#pragma unroll
    for (int q = 0; q < 4; q++) {
        float4 v = p1[q];
        br1[q*4+0] = v.x; br1[q*4+1] = v.y; br1[q*4+2] = v.z; br1[q*4+3] = v.w;
        v = p3[q];
        br3[q*4+0] = v.x; br3[q*4+1] = v.y; br3[q*4+2] = v.z; br3[q*4+3] = v.w;
    }
    int n = g_cnt[e];
    __shared__ float s1[16][RNK], s3[16][RNK];
    __shared__ int sr[16];
    for (int i0 = 0; i0 < n; i0 += 16) {
        int batch = min(16, n - i0);
        __syncthreads();
        int q = threadIdx.x;
        int j = q >> 5, v = q & 31;
        if (j < batch) {
            int row = g_lst[e * T_TOK + i0 + j];
            int t = row >> 1;
            if (v == 0) sr[j] = row;
            if (v < RNK) s1[j][v] = LSCALE * g_lrall[t * 256 + e * RNK + v];
            else         s3[j][v - RNK] = LSCALE * g_lrall[t * 256 + 128 + e * RNK + (v - RNK)];
        }
        __syncthreads();
        for (int jj = 0; jj < batch; jj++) {
            int row = sr[jj];
            int t = row >> 1;
            float h1 = __ldg(&g_base1[(size_t)t * FDIM + f]);
            float h3 = __ldg(&g_base3[(size_t)t * FDIM + f]);
#pragma unroll
            for (int r = 0; r < RNK; r++) {
                h1 = fmaf(s1[jj][r], br1[r], h1);
                h3 = fmaf(s3[jj][r], br3[r], h3);
            }
            float a = fast_silu(h1) * h3;
            g_act[(size_t)row * FDIM + f] = a;
            g_acth[(size_t)row * FDIM + f] = __float2half(a);
        }
    }
}

// ---------------- K6: expert-grouped LoRA-A down projection -----------------
#define L2FC 512
#define L2ST 516
__global__ void __launch_bounds__(256)
k_lora2g(const float* __restrict__ a2) {
    extern __shared__ float smf[];
    float* s_act = smf;
    float* s_a2  = smf + 32 * L2ST;
    int e = blockIdx.x, rb = blockIdx.y;
    int n = g_cnt[e];
    int r0 = rb * 32;
    if (r0 >= n) return;
    int nrows = min(32, n - r0);
    int tid = threadIdx.x;
    __shared__ int s_row[32];
    if (tid < 32) s_row[tid] = (tid < nrows) ? g_lst[e * T_TOK + r0 + tid] : -1;
    __syncthreads();
    int myrow = tid >> 3;
    int rp = (tid & 7) * 2;
    float acc0 = 0.f, acc1 = 0.f;
    for (int f0 = 0; f0 < FDIM; f0 += L2FC) {
        for (int q = tid; q < 32 * 128; q += 256) {
            int j = q >> 7, c4 = q & 127;
            float4 v = make_float4(0.f, 0.f, 0.f, 0.f);
            int row = s_row[j];
            if (row >= 0) v = *(const float4*)(g_act + (size_t)row * FDIM + f0 + c4 * 4);
            float* d = s_act + j * L2ST + c4 * 4;
            d[0] = v.x; d[1] = v.y; d[2] = v.z; d[3] = v.w;
        }
        for (int q = tid; q < 16 * 128; q += 256) {
            int j = q >> 7, c4 = q & 127;
            float4 v = *(const float4*)(a2 + ((size_t)e * RNK + j) * FDIM + f0 + c4 * 4);
            float* d = s_a2 + j * L2ST + c4 * 4;
            d[0] = v.x; d[1] = v.y; d[2] = v.z; d[3] = v.w;
        }
        __syncthreads();
        const float* ar0 = s_a2 + rp * L2ST;
        const float* ar1 = s_a2 + (rp + 1) * L2ST;
        const float* ac = s_act + myrow * L2ST;
#pragma unroll 8
        for (int f = 0; f < L2FC; f++) {
            float a = ac[f];
            acc0 = fmaf(a, ar0[f], acc0);
            acc1 = fmaf(a, ar1[f], acc1);
        }
        __syncthreads();
    }
    if (myrow < nrows) {
        int row = s_row[myrow];
        g_lr2[row * RNK + rp]     = LSCALE * acc0;
        g_lr2[row * RNK + rp + 1] = LSCALE * acc1;
    }
}

// ---------------- K8: LoRA-B down + expert mix (sums split-K halves) --------
__global__ void k_mix(const float* __restrict__ b2, float* __restrict__ out) {
    int t = blockIdx.x;
    __shared__ float l2[TOPK][RNK];
    __shared__ int   se[TOPK];
    __shared__ float sw[TOPK];
    if (threadIdx.x < TOPK * RNK) {
        int k = threadIdx.x / RNK, r = threadIdx.x % RNK;
        l2[k][r] = g_lr2[(t * TOPK + k) * RNK + r];
    }
    if (threadIdx.x < TOPK) {
        se[threadIdx.x] = g_idx[t * TOPK + threadIdx.x];
        sw[threadIdx.x] = g_wgt[t * TOPK + threadIdx.x];
    }
    __syncthreads();
    for (int d = threadIdx.x; d < DDIM; d += blockDim.x) {
        float o = 0.f;
#pragma unroll
        for (int k = 0; k < TOPK; k++) {
            int row = t * TOPK + k;
            float v = g_y[(size_t)row * DDIM + d] + g_y2[(size_t)row * DDIM + d];
            const float4* br = (const float4*)(b2 + ((size_t)se[k] * DDIM + d) * RNK);
#pragma unroll
            for (int q = 0; q < 4; q++) {
                float4 b = br[q];
                v += l2[k][q*4+0]*b.x + l2[k][q*4+1]*b.y + l2[k][q*4+2]*b.z + l2[k][q*4+3]*b.w;
            }
            o += sw[k] * v;
        }
        out[t * DDIM + d] = o;
    }
}

// ---------------- launch ----------------------------------------------------
extern "C" void kernel_launch(void* const* d_in, const int* in_sizes, int n_in,
                              void* d_out, int out_size) {
    const float* x      = (const float*)d_in[0];
    const float* norm_w = (const float*)d_in[1];
    const float* w1     = (const float*)d_in[2];
    const float* w3     = (const float*)d_in[3];
    const float* w2     = (const float*)d_in[4];
    const float* gate_w = (const float*)d_in[5];
    const float* a1     = (const float*)d_in[6];
    const float* b1     = (const float*)d_in[7];
    const float* a3     = (const float*)d_in[8];
    const float* b3     = (const float*)d_in[9];
    const float* a2     = (const float*)d_in[10];
    const float* b2     = (const float*)d_in[11];
    float* out = (float*)d_out;

    cudaFuncSetAttribute(k_lora2g, cudaFuncAttributeMaxDynamicSharedMemorySize,
                         48 * L2ST * 4);
    cudaFuncSetAttribute(k_up_gemm, cudaFuncAttributeMaxDynamicSharedMemorySize, GSM);
    cudaFuncSetAttribute(k_dn_gemm, cudaFuncAttributeMaxDynamicSharedMemorySize, GSM);

    // 1-2: weight conversions (fp32 -> fp16 scratch)
    k_cvt_up<<<(2 * FDIM * DDIM / 4) / 256, 256>>>(w1, w3);
    k_cvt_rest<<<(DDIM * FDIM / 4 + 2 * NEXP * RNK * DDIM / 4) / 256, 256>>>(w2, a1, a3);

    // 3-5
    k_rmsnorm<<<T_TOK, 256>>>(x, norm_w);
    k_router<<<T_TOK, 256>>>(gate_w);
    k_build<<<1, T_TOK * TOPK>>>();

    // 6: fused up projections + LoRA-A GEMM  (profiled launch)
    k_up_gemm<<<dim3(66, 4), 256, GSM>>>();

    // 7-8
    k_act2<<<dim3(NEXP, FDIM / 512), 512>>>(b1, b3);
    k_lora2g<<<dim3(NEXP, 16), 256, 48 * L2ST * 4>>>(a2);

    // 9: down projection, split-K x2
    k_dn_gemm<<<dim3(8, 8, 2), 256, GSM>>>();

    // 10
    k_mix<<<T_TOK, 256>>>(b2, out);
}

// round 7
// speedup vs baseline: 2.1952x; 1.4360x over previous
#include <cuda_runtime.h>
#include <cuda_fp16.h>
#include <cstdint>
#include <math.h>

#define T_TOK 512
#define DDIM  1024
#define FDIM  4096
#define NEXP  8
#define RNK   16
#define TOPK  2
#define LSCALE 2.0f
#define EPS   1e-6f

// ---------------- scratch (device globals) ----------------------------------
__device__ __half g_th[T_TOK * DDIM];
__device__ __half g_b1h[T_TOK * FDIM];
__device__ __half g_b3h[T_TOK * FDIM];
__device__ int    g_idx[T_TOK * TOPK];
__device__ float  g_wgt[T_TOK * TOPK];
__device__ __half g_acth[T_TOK * TOPK * FDIM];
__device__ float  g_lr2p[4][T_TOK * TOPK * RNK];    // split-F partials
__device__ float  g_yp[4][T_TOK * TOPK * DDIM];     // split-K partials
__device__ int    g_cnt[NEXP];
__device__ int    g_lst[NEXP * T_TOK];
__device__ __half g_w1h[FDIM * DDIM];
__device__ __half g_w3h[FDIM * DDIM];
__device__ __half g_w2h[DDIM * FDIM];
__device__ __half g_apkh[256 * DDIM];               // [a1 rows(128); a3 rows(128)]
__device__ float  g_lrall[T_TOK * 256];             // t @ apk^T (unscaled)

// ---------------- helpers ---------------------------------------------------
__device__ __forceinline__ uint32_t smem_to_u32(const void* p) {
    uint32_t a;
    asm("{ .reg .u64 t; cvta.to.shared.u64 t, %1; cvt.u32.u64 %0, t; }" : "=r"(a) : "l"(p));
    return a;
}
__device__ __forceinline__ uint32_t pack2(float lo, float hi) {
    __half2 h = __floats2half2_rn(lo, hi);
    return *reinterpret_cast<uint32_t*>(&h);
}
__device__ __forceinline__ void mma_f16(float* c, const uint32_t* a, const uint32_t* b) {
    asm volatile(
        "mma.sync.aligned.m16n8k16.row.col.f32.f16.f16.f32 "
        "{%0,%1,%2,%3}, {%4,%5,%6,%7}, {%8,%9}, {%0,%1,%2,%3};"
        : "+f"(c[0]), "+f"(c[1]), "+f"(c[2]), "+f"(c[3])
        : "r"(a[0]), "r"(a[1]), "r"(a[2]), "r"(a[3]), "r"(b[0]), "r"(b[1]));
}
#define CP_ASYNC16(dst, src) \
    asm volatile("cp.async.cg.shared.global [%0], [%1], 16;" :: "r"(dst), "l"(src))
#define CP_COMMIT() asm volatile("cp.async.commit_group;" ::: "memory")
#define CP_WAIT2()  asm volatile("cp.async.wait_group 2;" ::: "memory")

// ---------------- fast all-FMA silu (no MUFU) -------------------------------
__device__ __forceinline__ float fast_silu(float x) {
    float u = -x * 1.442695041f;
    float rn = u + 12582912.f;
    float n = rn - 12582912.f;
    float f = u - n;
    float p = 1.3333558146e-3f;
    p = fmaf(p, f, 9.6181291077e-3f);
    p = fmaf(p, f, 5.5504108664e-2f);
    p = fmaf(p, f, 2.4022650696e-1f);
    p = fmaf(p, f, 6.9314718056e-1f);
    p = fmaf(p, f, 1.0f);
    int ei = __float2int_rn(n);
    ei = ei > 60 ? 60 : (ei < -126 ? -126 : ei);
    float s = __int_as_float((ei + 127) << 23);
    float y = p * s;
    float d = 1.0f + y;
    float r = __int_as_float(0x7EF311C4 - __float_as_int(d));
    r = r * fmaf(-d, r, 2.0f);
    r = r * fmaf(-d, r, 2.0f);
    r = r * fmaf(-d, r, 2.0f);
    return x * r;
}

// ---------------- conversion kernels ----------------------------------------
__global__ void __launch_bounds__(256)
k_cvt_up(const float* __restrict__ w1, const float* __restrict__ w3) {
    const size_t n4 = (size_t)FDIM * DDIM / 4;
    size_t i = (size_t)blockIdx.x * 256 + threadIdx.x;
    float4 v;
    uint2* dst;
    if (i < n4) { v = ((const float4*)w1)[i]; dst = (uint2*)g_w1h + i; }
    else        { v = ((const float4*)w3)[i - n4]; dst = (uint2*)g_w3h + (i - n4); }
    *dst = make_uint2(pack2(v.x, v.y), pack2(v.z, v.w));
}
__global__ void __launch_bounds__(256)
k_cvt_rest(const float* __restrict__ w2, const float* __restrict__ a1,
           const float* __restrict__ a3) {
    const size_t n4w = (size_t)DDIM * FDIM / 4;
    const size_t n4a = (size_t)NEXP * RNK * DDIM / 4;
    size_t i = (size_t)blockIdx.x * 256 + threadIdx.x;
    float4 v;
    uint2* dst;
    if (i < n4w) { v = ((const float4*)w2)[i]; dst = (uint2*)g_w2h + i; }
    else {
        size_t j = i - n4w;
        if (j < n4a) { v = ((const float4*)a1)[j]; dst = (uint2*)g_apkh + j; }
        else         { v = ((const float4*)a3)[j - n4a]; dst = (uint2*)g_apkh + (j - n4a) + n4a; }
    }
    *dst = make_uint2(pack2(v.x, v.y), pack2(v.z, v.w));
}

// ---------------- K1: RMSNorm + router fused --------------------------------
__global__ void __launch_bounds__(256)
k_rmsnorm_rt(const float* __restrict__ x, const float* __restrict__ nw,
             const float* __restrict__ gw) {
    __shared__ float s_t[DDIM];
    __shared__ float sred[32];
    __shared__ float logits[NEXP];
    int t = blockIdx.x;
    const float* xr = x + t * DDIM;
    float ss = 0.f;
    for (int i = threadIdx.x; i < DDIM; i += 256) {
        float v = xr[i];
        ss += v * v;
    }
    for (int o = 16; o; o >>= 1) ss += __shfl_xor_sync(0xffffffffu, ss, o);
    if ((threadIdx.x & 31) == 0) sred[threadIdx.x >> 5] = ss;
    __syncthreads();
    if (threadIdx.x < 32) {
        float v = (threadIdx.x < 8) ? sred[threadIdx.x] : 0.f;
        for (int o = 4; o; o >>= 1) v += __shfl_xor_sync(0xffffffffu, v, o);
        if (threadIdx.x == 0) sred[0] = v;
    }
    __syncthreads();
    float scale = rsqrtf(sred[0] / (float)DDIM + EPS);
    for (int i = threadIdx.x; i < DDIM; i += 256) {
        float v = xr[i] * scale * nw[i];
        s_t[i] = v;
        g_th[t * DDIM + i] = __float2half(v);
    }
    __syncthreads();
    int w = threadIdx.x >> 5, l = threadIdx.x & 31;   // warp = expert
    const float* gr = gw + w * DDIM;
    float s = 0.f;
    for (int i = l; i < DDIM; i += 32) s += s_t[i] * gr[i];
    for (int o = 16; o; o >>= 1) s += __shfl_xor_sync(0xffffffffu, s, o);
    if (l == 0) logits[w] = s;
    __syncthreads();
    if (threadIdx.x == 0) {
        float mx = logits[0];
        for (int e = 1; e < NEXP; e++) mx = fmaxf(mx, logits[e]);
        float p[NEXP], sum = 0.f;
        for (int e = 0; e < NEXP; e++) { p[e] = expf(logits[e] - mx); sum += p[e]; }
        for (int e = 0; e < NEXP; e++) p[e] /= sum;
        int i0 = 0;
        for (int e = 1; e < NEXP; e++) if (p[e] > p[i0]) i0 = e;
        int i1 = -1;
        for (int e = 0; e < NEXP; e++) {
            if (e == i0) continue;
            if (i1 < 0 || p[e] > p[i1]) i1 = e;
        }
        float w0 = p[i0], w1 = p[i1], tw = w0 + w1;
        g_idx[t * 2 + 0] = i0;  g_idx[t * 2 + 1] = i1;
        g_wgt[t * 2 + 0] = w0 / tw;  g_wgt[t * 2 + 1] = w1 / tw;
    }
}

// ---------------- K2b: per-expert row lists ---------------------------------
__global__ void k_build() {
    int tid = threadIdx.x;
    if (tid < NEXP) g_cnt[tid] = 0;
    __syncthreads();
    int e = g_idx[tid];
    int pos = atomicAdd(&g_cnt[e], 1);
    g_lst[e * T_TOK + pos] = tid;
}

// ============================================================================
// cp.async 4-stage fp16 GEMM core (tile 128x128, BK=32, 256 thr, 8 warps 2x4,
// warp tile 64x32). HALF_OUT selects fp16 vs fp32 C.
// ============================================================================
#define SSTG 5120
#define GSM  (4 * SSTG * 4)

template<bool HOUT>
__device__ __forceinline__ void gemm_core(
    const __half* __restrict__ Arow, const __half* __restrict__ Brow,
    void* __restrict__ Cv, int N, int niter, int bm, int bn,
    uint32_t* sm, uint32_t smb) {
    int tid = threadIdx.x;
    int wid = tid >> 5, lane = tid & 31;
    int qr = lane >> 2, qc = lane & 3;
    int wm = wid & 1, wn = wid >> 1;

    const __half* gsrc = (tid < 128) ? Arow : Brow;
    uint32_t srow_b = smb + (uint32_t)tid * 80u;

    float acc[4][4][4];
#pragma unroll
    for (int i = 0; i < 4; i++)
#pragma unroll
        for (int j = 0; j < 4; j++)
#pragma unroll
            for (int q = 0; q < 4; q++) acc[i][j][q] = 0.f;

#pragma unroll
    for (int s = 0; s < 3; s++) {
        if (s < niter) {
            const __half* src = gsrc + s * 32;
            uint32_t d = srow_b + (uint32_t)s * 20480u;
#pragma unroll
            for (int c = 0; c < 4; c++) CP_ASYNC16(d + c * 16, src + c * 8);
        }
        CP_COMMIT();
    }

    for (int it = 0; it < niter; ++it) {
        CP_WAIT2();
        __syncthreads();
        int nx = it + 3;
        if (nx < niter) {
            const __half* src = gsrc + nx * 32;
            uint32_t d = srow_b + (uint32_t)(nx & 3) * 20480u;
#pragma unroll
            for (int c = 0; c < 4; c++) CP_ASYNC16(d + c * 16, src + c * 8);
        }
        CP_COMMIT();

        const uint32_t* st = sm + (it & 3) * SSTG;
#pragma unroll
        for (int g = 0; g < 2; ++g) {
            uint32_t af[4][4], bf[4][2];
#pragma unroll
            for (int mt = 0; mt < 4; mt++) {
                uint32_t r0 = (uint32_t)(wm * 64 + mt * 16 + qr) * 20u + g * 8 + qc;
                af[mt][0] = st[r0];
                af[mt][1] = st[r0 + 8 * 20];
                af[mt][2] = st[r0 + 4];
                af[mt][3] = st[r0 + 8 * 20 + 4];
            }
#pragma unroll
            for (int nt = 0; nt < 4; nt++) {
                uint32_t r0 = (uint32_t)(128 + wn * 32 + nt * 8 + qr) * 20u + g * 8 + qc;
                bf[nt][0] = st[r0];
                bf[nt][1] = st[r0 + 4];
            }
#pragma unroll
            for (int mt = 0; mt < 4; mt++)
#pragma unroll
                for (int nt = 0; nt < 4; nt++)
                    mma_f16(acc[mt][nt], af[mt], bf[nt]);
        }
    }

#pragma unroll
    for (int mt = 0; mt < 4; mt++)
#pragma unroll
        for (int nt = 0; nt < 4; nt++) {
            int row0 = bm + wm * 64 + mt * 16 + qr;
            int col  = bn + wn * 32 + nt * 8 + 2 * qc;
            if (HOUT) {
                __half* C = (__half*)Cv;
                *(uint32_t*)&C[(size_t)row0 * N + col] =
                    pack2(acc[mt][nt][0], acc[mt][nt][1]);
                *(uint32_t*)&C[(size_t)(row0 + 8) * N + col] =
                    pack2(acc[mt][nt][2], acc[mt][nt][3]);
            } else {
                float* C = (float*)Cv;
                *(float2*)&C[(size_t)row0 * N + col] =
                    make_float2(acc[mt][nt][0], acc[mt][nt][1]);
                *(float2*)&C[(size_t)(row0 + 8) * N + col] =
                    make_float2(acc[mt][nt][2], acc[mt][nt][3]);
            }
        }
}

// fused up GEMM: segments w1 | w3 (fp16 out) | apk (fp32 out)
__global__ void __launch_bounds__(256)
k_up_gemm() {
    extern __shared__ uint32_t sm[];
    uint32_t smb = smem_to_u32(sm);
    int bx = blockIdx.x;
    int bm = blockIdx.y * 128;
    int tid = threadIdx.x;
    const __half* Arow = g_th + (size_t)(bm + tid) * DDIM;
    if (bx < 64) {
        const __half* B = (bx < 32) ? g_w1h : g_w3h;
        __half* C = (bx < 32) ? g_b1h : g_b3h;
        int bn = (bx & 31) * 128;
        const __half* Brow = B + (size_t)(bn + (tid - 128)) * DDIM;
        gemm_core<true>(Arow, Brow, C, FDIM, DDIM / 32, bm, bn, sm, smb);
    } else {
        int bn = (bx - 64) * 128;
        const __half* Brow = g_apkh + (size_t)(bn + (tid - 128)) * DDIM;
        gemm_core<false>(Arow, Brow, g_lrall, 256, DDIM / 32, bm, bn, sm, smb);
    }
}

// down GEMM, split-K x4
__global__ void __launch_bounds__(256)
k_dn_gemm() {
    extern __shared__ uint32_t sm[];
    uint32_t smb = smem_to_u32(sm);
    int bm = blockIdx.y * 128, bn = blockIdx.x * 128;
    int kz = blockIdx.z;
    int kOff = kz * (FDIM / 4);
    int tid = threadIdx.x;
    const __half* Arow = g_acth + (size_t)(bm + tid) * FDIM + kOff;
    const __half* Brow = g_w2h + (size_t)(bn + (tid - 128)) * FDIM + kOff;
    gemm_core<false>(Arow, Brow, g_yp[kz], DDIM, (FDIM / 4) / 32, bm, bn, sm, smb);
}

// ---------------- K5: expert-grouped LoRA-B + SwiGLU ------------------------
// grid (E, 16), 256 threads; f = by*256+tid; rows unrolled x2.
__global__ void __launch_bounds__(256)
k_act2(const float* __restrict__ b1, const float* __restrict__ b3) {
    int e = blockIdx.x;
    int f = blockIdx.y * 256 + threadIdx.x;
    float br1[RNK], br3[RNK];
    const float4* p1 = (const float4*)(b1 + ((size_t)e * FDIM + f) * RNK);
    const float4* p3 = (const float4*)(b3 + ((size_t)e * FDIM + f) * RNK);
#pragma unroll
    for (int q = 0; q < 4; q++) {
        float4 v = p1[q];
        br1[q*4+0] = v.x; br1[q*4+1] = v.y; br1[q*4+2] = v.z; br1[q*4+3] = v.w;
        v = p3[q];
        br3[q*4+0] = v.x; br3[q*4+1] = v.y; br3[q*4+2] = v.z; br3[q*4+3] = v.w;
    }
    int n = g_cnt[e];
    __shared__ float s1[16][RNK], s3[16][RNK];
    __shared__ int sr[16];
    for (int i0 = 0; i0 < n; i0 += 16) {
        int batch = min(16, n - i0);
        __syncthreads();
        {
            int j = threadIdx.x >> 4, v = threadIdx.x & 15;
            if (j < batch) {
                int row = g_lst[e * T_TOK + i0 + j];
                int t = row >> 1;
                if (v == 0) sr[j] = row;
                s1[j][v] = LSCALE * g_lrall[t * 256 + e * RNK + v];
                s3[j][v] = LSCALE * g_lrall[t * 256 + 128 + e * RNK + v];
            }
        }
        __syncthreads();
        int jj = 0;
        for (; jj + 2 <= batch; jj += 2) {
            int rowA = sr[jj], rowB = sr[jj + 1];
            int tA = rowA >> 1, tB = rowB >> 1;
            float h1a = __half2float(g_b1h[(size_t)tA * FDIM + f]);
            float h3a = __half2float(g_b3h[(size_t)tA * FDIM + f]);
            float h1b = __half2float(g_b1h[(size_t)tB * FDIM + f]);
            float h3b = __half2float(g_b3h[(size_t)tB * FDIM + f]);
#pragma unroll
            for (int r = 0; r < RNK; r++) {
                h1a = fmaf(s1[jj][r], br1[r], h1a);
                h3a = fmaf(s3[jj][r], br3[r], h3a);
                h1b = fmaf(s1[jj + 1][r], br1[r], h1b);
                h3b = fmaf(s3[jj + 1][r], br3[r], h3b);
            }
            g_acth[(size_t)rowA * FDIM + f] = __float2half(fast_silu(h1a) * h3a);
            g_acth[(size_t)rowB * FDIM + f] = __float2half(fast_silu(h1b) * h3b);
        }
        if (jj < batch) {
            int row = sr[jj];
            int t = row >> 1;
            float h1 = __half2float(g_b1h[(size_t)t * FDIM + f]);
            float h3 = __half2float(g_b3h[(size_t)t * FDIM + f]);
#pragma unroll
            for (int r = 0; r < RNK; r++) {
                h1 = fmaf(s1[jj][r], br1[r], h1);
                h3 = fmaf(s3[jj][r], br3[r], h3);
            }
            g_acth[(size_t)row * FDIM + f] = __float2half(fast_silu(h1) * h3);
        }
    }
}

// ---------------- K6: expert-grouped LoRA-A down proj, F-split x4 -----------
#define L2FC 512
#define L2ST 516
__global__ void __launch_bounds__(256)
k_lora2g(const float* __restrict__ a2) {
    extern __shared__ float smf[];
    float* s_act = smf;                  // [32][516]
    float* s_a2  = smf + 32 * L2ST;      // [16][516]
    int e = blockIdx.x, rb = blockIdx.y, bz = blockIdx.z;
    int n = g_cnt[e];
    int r0 = rb * 32;
    if (r0 >= n) return;
    int nrows = min(32, n - r0);
    int tid = threadIdx.x;
    __shared__ int s_row[32];
    if (tid < 32) s_row[tid] = (tid < nrows) ? g_lst[e * T_TOK + r0 + tid] : -1;
    __syncthreads();
    int myrow = tid >> 3;
    int rp = (tid & 7) * 2;
    float acc0 = 0.f, acc1 = 0.f;
    int fbeg = bz * (FDIM / 4);
    for (int f0 = fbeg; f0 < fbeg + FDIM / 4; f0 += L2FC) {
        // act (fp16 -> fp32 smem): 32 rows x 64 uint4 (8 halves each)
        for (int q = tid; q < 32 * 64; q += 256) {
            int j = q >> 6, c = q & 63;
            float* d = s_act + j * L2ST + c * 8;
            int row = s_row[j];
            if (row >= 0) {
                uint4 v = *(const uint4*)(g_acth + (size_t)row * FDIM + f0 + c * 8);
                __half2 h0 = *(__half2*)&v.x, h1 = *(__half2*)&v.y;
                __half2 h2 = *(__half2*)&v.z, h3 = *(__half2*)&v.w;
                float2 f0v = __half22float2(h0), f1v = __half22float2(h1);
                float2 f2v = __half22float2(h2), f3v = __half22float2(h3);
                d[0] = f0v.x; d[1] = f0v.y; d[2] = f1v.x; d[3] = f1v.y;
                d[4] = f2v.x; d[5] = f2v.y; d[6] = f3v.x; d[7] = f3v.y;
            } else {
                for (int z = 0; z < 8; z++) d[z] = 0.f;
            }
        }
        // a2 (fp32): 16 rows x 128 float4
        for (int q = tid; q < 16 * 128; q += 256) {
            int j = q >> 7, c4 = q & 127;
            float4 v = *(const float4*)(a2 + ((size_t)e * RNK + j) * FDIM + f0 + c4 * 4);
            float* d = s_a2 + j * L2ST + c4 * 4;
            d[0] = v.x; d[1] = v.y; d[2] = v.z; d[3] = v.w;
        }
        __syncthreads();
        const float* ar0 = s_a2 + rp * L2ST;
        const float* ar1 = s_a2 + (rp + 1) * L2ST;
        const float* ac = s_act + myrow * L2ST;
#pragma unroll 8
        for (int f = 0; f < L2FC; f++) {
            float a = ac[f];
            acc0 = fmaf(a, ar0[f], acc0);
            acc1 = fmaf(a, ar1[f], acc1);
        }
        __syncthreads();
    }
    if (myrow < nrows) {
        int row = s_row[myrow];
        g_lr2p[bz][row * RNK + rp]     = LSCALE * acc0;
        g_lr2p[bz][row * RNK + rp + 1] = LSCALE * acc1;
    }
}

// ---------------- K8: LoRA-B down + expert mix (sums partials) --------------
__global__ void k_mix(const float* __restrict__ b2, float* __restrict__ out) {
    int t = blockIdx.x;
    __shared__ float l2[TOPK][RNK];
    __shared__ int   se[TOPK];
    __shared__ float sw[TOPK];
    if (threadIdx.x < TOPK * RNK) {
        int k = threadIdx.x / RNK, r = threadIdx.x % RNK;
        int off = (t * TOPK + k) * RNK + r;
        l2[k][r] = g_lr2p[0][off] + g_lr2p[1][off] + g_lr2p[2][off] + g_lr2p[3][off];
    }
    if (threadIdx.x < TOPK) {
        se[threadIdx.x] = g_idx[t * TOPK + threadIdx.x];
        sw[threadIdx.x] = g_wgt[t * TOPK + threadIdx.x];
    }
    __syncthreads();
    for (int d = threadIdx.x; d < DDIM; d += blockDim.x) {
        float o = 0.f;
#pragma unroll
        for (int k = 0; k < TOPK; k++) {
            size_t off = (size_t)(t * TOPK + k) * DDIM + d;
            float v = g_yp[0][off] + g_yp[1][off] + g_yp[2][off] + g_yp[3][off];
            const float4* br = (const float4*)(b2 + ((size_t)se[k] * DDIM + d) * RNK);
#pragma unroll
            for (int q = 0; q < 4; q++) {
                float4 b = br[q];
                v += l2[k][q*4+0]*b.x + l2[k][q*4+1]*b.y + l2[k][q*4+2]*b.z + l2[k][q*4+3]*b.w;
            }
            o += sw[k] * v;
        }
        out[t * DDIM + d] = o;
    }
}

// ---------------- launch ----------------------------------------------------
extern "C" void kernel_launch(void* const* d_in, const int* in_sizes, int n_in,
                              void* d_out, int out_size) {
    const float* x      = (const float*)d_in[0];
    const float* norm_w = (const float*)d_in[1];
    const float* w1     = (const float*)d_in[2];
    const float* w3     = (const float*)d_in[3];
    const float* w2     = (const float*)d_in[4];
    const float* gate_w = (const float*)d_in[5];
    const float* a1     = (const float*)d_in[6];
    const float* b1     = (const float*)d_in[7];
    const float* a3     = (const float*)d_in[8];
    const float* b3     = (const float*)d_in[9];
    const float* a2     = (const float*)d_in[10];
    const float* b2     = (const float*)d_in[11];
    float* out = (float*)d_out;

    cudaFuncSetAttribute(k_lora2g, cudaFuncAttributeMaxDynamicSharedMemorySize,
                         48 * L2ST * 4);
    cudaFuncSetAttribute(k_up_gemm, cudaFuncAttributeMaxDynamicSharedMemorySize, GSM);
    cudaFuncSetAttribute(k_dn_gemm, cudaFuncAttributeMaxDynamicSharedMemorySize, GSM);

    k_cvt_up<<<(2 * FDIM * DDIM / 4) / 256, 256>>>(w1, w3);
    k_cvt_rest<<<(DDIM * FDIM / 4 + 2 * NEXP * RNK * DDIM / 4) / 256, 256>>>(w2, a1, a3);

    k_rmsnorm_rt<<<T_TOK, 256>>>(x, norm_w, gate_w);
    k_build<<<1, T_TOK * TOPK>>>();

    k_up_gemm<<<dim3(66, 4), 256, GSM>>>();

    k_act2<<<dim3(NEXP, FDIM / 256), 256>>>(b1, b3);
    k_lora2g<<<dim3(NEXP, 16, 4), 256, 48 * L2ST * 4>>>(a2);

    k_dn_gemm<<<dim3(8, 8, 4), 256, GSM>>>();

    k_mix<<<T_TOK, 256>>>(b2, out);
}

// round 8
// speedup vs baseline: 2.4838x; 1.1315x over previous
#include <cuda_runtime.h>
#include <cuda_fp16.h>
#include <cstdint>
#include <math.h>

#define T_TOK 512
#define DDIM  1024
#define FDIM  4096
#define NEXP  8
#define RNK   16
#define TOPK  2
#define LSCALE 2.0f
#define EPS   1e-6f

// ---------------- scratch (device globals) ----------------------------------
__device__ __half g_th[T_TOK * DDIM];
__device__ __half g_b1h[T_TOK * FDIM];
__device__ __half g_b3h[T_TOK * FDIM];
__device__ int    g_idx[T_TOK * TOPK];
__device__ float  g_wgt[T_TOK * TOPK];
__device__ __half g_acth[T_TOK * TOPK * FDIM];
__device__ float  g_lr2p[8][T_TOK * TOPK * RNK];    // split-F partials
__device__ float  g_yp[4][T_TOK * TOPK * DDIM];     // split-K partials
__device__ int    g_cnt[NEXP];
__device__ int    g_lst[NEXP * T_TOK];
__device__ __half g_w1h[FDIM * DDIM];
__device__ __half g_w3h[FDIM * DDIM];
__device__ __half g_w2h[DDIM * FDIM];
__device__ __half g_apkh[256 * DDIM];               // [a1 rows(128); a3 rows(128)]
__device__ float  g_lrall[T_TOK * 256];             // t @ apk^T (unscaled)

// ---------------- helpers ---------------------------------------------------
__device__ __forceinline__ uint32_t smem_to_u32(const void* p) {
    uint32_t a;
    asm("{ .reg .u64 t; cvta.to.shared.u64 t, %1; cvt.u32.u64 %0, t; }" : "=r"(a) : "l"(p));
    return a;
}
__device__ __forceinline__ uint32_t pack2(float lo, float hi) {
    __half2 h = __floats2half2_rn(lo, hi);
    return *reinterpret_cast<uint32_t*>(&h);
}
__device__ __forceinline__ void mma_f16(float* c, const uint32_t* a, const uint32_t* b) {
    asm volatile(
        "mma.sync.aligned.m16n8k16.row.col.f32.f16.f16.f32 "
        "{%0,%1,%2,%3}, {%4,%5,%6,%7}, {%8,%9}, {%0,%1,%2,%3};"
        : "+f"(c[0]), "+f"(c[1]), "+f"(c[2]), "+f"(c[3])
        : "r"(a[0]), "r"(a[1]), "r"(a[2]), "r"(a[3]), "r"(b[0]), "r"(b[1]));
}
#define CP_ASYNC16(dst, src) \
    asm volatile("cp.async.cg.shared.global [%0], [%1], 16;" :: "r"(dst), "l"(src))
#define CP_COMMIT() asm volatile("cp.async.commit_group;" ::: "memory")
#define CP_WAIT2()  asm volatile("cp.async.wait_group 2;" ::: "memory")

// ---------------- fast all-FMA silu (no MUFU) -------------------------------
__device__ __forceinline__ float fast_silu(float x) {
    float u = -x * 1.442695041f;
    float rn = u + 12582912.f;
    float n = rn - 12582912.f;
    float f = u - n;
    float p = 1.3333558146e-3f;
    p = fmaf(p, f, 9.6181291077e-3f);
    p = fmaf(p, f, 5.5504108664e-2f);
    p = fmaf(p, f, 2.4022650696e-1f);
    p = fmaf(p, f, 6.9314718056e-1f);
    p = fmaf(p, f, 1.0f);
    int ei = __float2int_rn(n);
    ei = ei > 60 ? 60 : (ei < -126 ? -126 : ei);
    float s = __int_as_float((ei + 127) << 23);
    float y = p * s;
    float d = 1.0f + y;
    float r = __int_as_float(0x7EF311C4 - __float_as_int(d));
    r = r * fmaf(-d, r, 2.0f);
    r = r * fmaf(-d, r, 2.0f);
    r = r * fmaf(-d, r, 2.0f);
    return x * r;
}

// ---------------- merged conversion kernel ----------------------------------
__global__ void __launch_bounds__(256)
k_cvt_all(const float* __restrict__ w1, const float* __restrict__ w3,
          const float* __restrict__ w2, const float* __restrict__ a1,
          const float* __restrict__ a3) {
    const size_t n4 = (size_t)FDIM * DDIM / 4;          // 1M per up matrix
    const size_t n4w = (size_t)DDIM * FDIM / 4;         // 1M
    const size_t n4a = (size_t)NEXP * RNK * DDIM / 4;   // 32768
    size_t i = (size_t)blockIdx.x * 256 + threadIdx.x;
    float4 v;
    uint2* dst;
    if (i < n4)              { v = ((const float4*)w1)[i]; dst = (uint2*)g_w1h + i; }
    else if (i < 2 * n4)     { v = ((const float4*)w3)[i - n4]; dst = (uint2*)g_w3h + (i - n4); }
    else if (i < 2 * n4 + n4w) { size_t j = i - 2 * n4; v = ((const float4*)w2)[j]; dst = (uint2*)g_w2h + j; }
    else {
        size_t j = i - 2 * n4 - n4w;
        if (j < n4a) { v = ((const float4*)a1)[j]; dst = (uint2*)g_apkh + j; }
        else         { v = ((const float4*)a3)[j - n4a]; dst = (uint2*)g_apkh + (j - n4a) + n4a; }
    }
    *dst = make_uint2(pack2(v.x, v.y), pack2(v.z, v.w));
}

// ---------------- K1: RMSNorm + router fused --------------------------------
__global__ void __launch_bounds__(256)
k_rmsnorm_rt(const float* __restrict__ x, const float* __restrict__ nw,
             const float* __restrict__ gw) {
    __shared__ float s_t[DDIM];
    __shared__ float sred[32];
    __shared__ float logits[NEXP];
    int t = blockIdx.x;
    const float* xr = x + t * DDIM;
    float ss = 0.f;
    for (int i = threadIdx.x; i < DDIM; i += 256) {
        float v = xr[i];
        ss += v * v;
    }
    for (int o = 16; o; o >>= 1) ss += __shfl_xor_sync(0xffffffffu, ss, o);
    if ((threadIdx.x & 31) == 0) sred[threadIdx.x >> 5] = ss;
    __syncthreads();
    if (threadIdx.x < 32) {
        float v = (threadIdx.x < 8) ? sred[threadIdx.x] : 0.f;
        for (int o = 4; o; o >>= 1) v += __shfl_xor_sync(0xffffffffu, v, o);
        if (threadIdx.x == 0) sred[0] = v;
    }
    __syncthreads();
    float scale = rsqrtf(sred[0] / (float)DDIM + EPS);
    for (int i = threadIdx.x; i < DDIM; i += 256) {
        float v = xr[i] * scale * nw[i];
        s_t[i] = v;
        g_th[t * DDIM + i] = __float2half(v);
    }
    __syncthreads();
    int w = threadIdx.x >> 5, l = threadIdx.x & 31;
    const float* gr = gw + w * DDIM;
    float s = 0.f;
    for (int i = l; i < DDIM; i += 32) s += s_t[i] * gr[i];
    for (int o = 16; o; o >>= 1) s += __shfl_xor_sync(0xffffffffu, s, o);
    if (l == 0) logits[w] = s;
    __syncthreads();
    if (threadIdx.x == 0) {
        float mx = logits[0];
        for (int e = 1; e < NEXP; e++) mx = fmaxf(mx, logits[e]);
        float p[NEXP], sum = 0.f;
        for (int e = 0; e < NEXP; e++) { p[e] = expf(logits[e] - mx); sum += p[e]; }
        for (int e = 0; e < NEXP; e++) p[e] /= sum;
        int i0 = 0;
        for (int e = 1; e < NEXP; e++) if (p[e] > p[i0]) i0 = e;
        int i1 = -1;
        for (int e = 0; e < NEXP; e++) {
            if (e == i0) continue;
            if (i1 < 0 || p[e] > p[i1]) i1 = e;
        }
        float w0 = p[i0], w1 = p[i1], tw = w0 + w1;
        g_idx[t * 2 + 0] = i0;  g_idx[t * 2 + 1] = i1;
        g_wgt[t * 2 + 0] = w0 / tw;  g_wgt[t * 2 + 1] = w1 / tw;
    }
}

// ---------------- K2b: per-expert lists, deterministic (no atomics) ---------
__global__ void __launch_bounds__(1024) k_build() {
    __shared__ unsigned char s_e[T_TOK * TOPK];
    int tid = threadIdx.x;
    int e = g_idx[tid];
    s_e[tid] = (unsigned char)e;
    __syncthreads();
    // pos = count of equal experts among rows < tid (stable order)
    const uint32_t* se4 = (const uint32_t*)s_e;
    uint32_t pat = (uint32_t)e * 0x01010101u;
    int full = tid >> 2;
    int pos = 0;
    for (int i = 0; i < full; i++)
        pos += __popc(__vcmpeq4(se4[i], pat) & 0x01010101u);
    for (int i = full * 4; i < tid; i++) pos += (s_e[i] == e);
    g_lst[e * T_TOK + pos] = tid;
    if (tid < NEXP) {
        uint32_t patc = (uint32_t)tid * 0x01010101u;
        int c = 0;
        for (int i = 0; i < (T_TOK * TOPK) / 4; i++)
            c += __popc(__vcmpeq4(se4[i], patc) & 0x01010101u);
        g_cnt[tid] = c;
    }
}

// ============================================================================
// cp.async 4-stage fp16 GEMM core (tile 128x128, BK=32, 256 thr, 8 warps 2x4,
// warp tile 64x32). HOUT selects fp16 vs fp32 C.
// ============================================================================
#define SSTG 5120
#define GSM  (4 * SSTG * 4)

template<bool HOUT>
__device__ __forceinline__ void gemm_core(
    const __half* __restrict__ Arow, const __half* __restrict__ Brow,
    void* __restrict__ Cv, int N, int niter, int bm, int bn,
    uint32_t* sm, uint32_t smb) {
    int tid = threadIdx.x;
    int wid = tid >> 5, lane = tid & 31;
    int qr = lane >> 2, qc = lane & 3;
    int wm = wid & 1, wn = wid >> 1;

    const __half* gsrc = (tid < 128) ? Arow : Brow;
    uint32_t srow_b = smb + (uint32_t)tid * 80u;

    float acc[4][4][4];
#pragma unroll
    for (int i = 0; i < 4; i++)
#pragma unroll
        for (int j = 0; j < 4; j++)
#pragma unroll
            for (int q = 0; q < 4; q++) acc[i][j][q] = 0.f;

#pragma unroll
    for (int s = 0; s < 3; s++) {
        if (s < niter) {
            const __half* src = gsrc + s * 32;
            uint32_t d = srow_b + (uint32_t)s * 20480u;
#pragma unroll
            for (int c = 0; c < 4; c++) CP_ASYNC16(d + c * 16, src + c * 8);
        }
        CP_COMMIT();
    }

    for (int it = 0; it < niter; ++it) {
        CP_WAIT2();
        __syncthreads();
        int nx = it + 3;
        if (nx < niter) {
            const __half* src = gsrc + nx * 32;
            uint32_t d = srow_b + (uint32_t)(nx & 3) * 20480u;
#pragma unroll
            for (int c = 0; c < 4; c++) CP_ASYNC16(d + c * 16, src + c * 8);
        }
        CP_COMMIT();

        const uint32_t* st = sm + (it & 3) * SSTG;
#pragma unroll
        for (int g = 0; g < 2; ++g) {
            uint32_t af[4][4], bf[4][2];
#pragma unroll
            for (int mt = 0; mt < 4; mt++) {
                uint32_t r0 = (uint32_t)(wm * 64 + mt * 16 + qr) * 20u + g * 8 + qc;
                af[mt][0] = st[r0];
                af[mt][1] = st[r0 + 8 * 20];
                af[mt][2] = st[r0 + 4];
                af[mt][3] = st[r0 + 8 * 20 + 4];
            }
#pragma unroll
            for (int nt = 0; nt < 4; nt++) {
                uint32_t r0 = (uint32_t)(128 + wn * 32 + nt * 8 + qr) * 20u + g * 8 + qc;
                bf[nt][0] = st[r0];
                bf[nt][1] = st[r0 + 4];
            }
#pragma unroll
            for (int mt = 0; mt < 4; mt++)
#pragma unroll
                for (int nt = 0; nt < 4; nt++)
                    mma_f16(acc[mt][nt], af[mt], bf[nt]);
        }
    }

#pragma unroll
    for (int mt = 0; mt < 4; mt++)
#pragma unroll
        for (int nt = 0; nt < 4; nt++) {
            int row0 = bm + wm * 64 + mt * 16 + qr;
            int col  = bn + wn * 32 + nt * 8 + 2 * qc;
            if (HOUT) {
                __half* C = (__half*)Cv;
                *(uint32_t*)&C[(size_t)row0 * N + col] =
                    pack2(acc[mt][nt][0], acc[mt][nt][1]);
                *(uint32_t*)&C[(size_t)(row0 + 8) * N + col] =
                    pack2(acc[mt][nt][2], acc[mt][nt][3]);
            } else {
                float* C = (float*)Cv;
                *(float2*)&C[(size_t)row0 * N + col] =
                    make_float2(acc[mt][nt][0], acc[mt][nt][1]);
                *(float2*)&C[(size_t)(row0 + 8) * N + col] =
                    make_float2(acc[mt][nt][2], acc[mt][nt][3]);
            }
        }
}

// fused up GEMM: segments w1 | w3 (fp16 out) | apk (fp32 out)
__global__ void __launch_bounds__(256)
k_up_gemm() {
    extern __shared__ uint32_t sm[];
    uint32_t smb = smem_to_u32(sm);
    int bx = blockIdx.x;
    int bm = blockIdx.y * 128;
    int tid = threadIdx.x;
    const __half* Arow = g_th + (size_t)(bm + tid) * DDIM;
    if (bx < 64) {
        const __half* B = (bx < 32) ? g_w1h : g_w3h;
        __half* C = (bx < 32) ? g_b1h : g_b3h;
        int bn = (bx & 31) * 128;
        const __half* Brow = B + (size_t)(bn + (tid - 128)) * DDIM;
        gemm_core<true>(Arow, Brow, C, FDIM, DDIM / 32, bm, bn, sm, smb);
    } else {
        int bn = (bx - 64) * 128;
        const __half* Brow = g_apkh + (size_t)(bn + (tid - 128)) * DDIM;
        gemm_core<false>(Arow, Brow, g_lrall, 256, DDIM / 32, bm, bn, sm, smb);
    }
}

// down GEMM, split-K x4
__global__ void __launch_bounds__(256)
k_dn_gemm() {
    extern __shared__ uint32_t sm[];
    uint32_t smb = smem_to_u32(sm);
    int bm = blockIdx.y * 128, bn = blockIdx.x * 128;
    int kz = blockIdx.z;
    int kOff = kz * (FDIM / 4);
    int tid = threadIdx.x;
    const __half* Arow = g_acth + (size_t)(bm + tid) * FDIM + kOff;
    const __half* Brow = g_w2h + (size_t)(bn + (tid - 128)) * FDIM + kOff;
    gemm_core<false>(Arow, Brow, g_yp[kz], DDIM, (FDIM / 4) / 32, bm, bn, sm, smb);
}

// ---------------- K5: expert-grouped LoRA-B + SwiGLU, row-split x4 ----------
__global__ void __launch_bounds__(256)
k_act2(const float* __restrict__ b1, const float* __restrict__ b3) {
    int e = blockIdx.x;
    int f = blockIdx.y * 256 + threadIdx.x;
    int bz = blockIdx.z;
    float br1[RNK], br3[RNK];
    const float4* p1 = (const float4*)(b1 + ((size_t)e * FDIM + f) * RNK);
    const float4* p3 = (const float4*)(b3 + ((size_t)e * FDIM + f) * RNK);
#pragma unroll
    for (int q = 0; q < 4; q++) {
        float4 v = p1[q];
        br1[q*4+0] = v.x; br1[q*4+1] = v.y; br1[q*4+2] = v.z; br1[q*4+3] = v.w;
        v = p3[q];
        br3[q*4+0] = v.x; br3[q*4+1] = v.y; br3[q*4+2] = v.z; br3[q*4+3] = v.w;
    }
    int n = g_cnt[e];
    __shared__ float s1[16][RNK], s3[16][RNK];
    __shared__ int sr[16];
    for (int i0 = bz * 16; i0 < n; i0 += 64) {
        int batch = min(16, n - i0);
        __syncthreads();
        {
            int j = threadIdx.x >> 4, v = threadIdx.x & 15;
            if (j < batch) {
                int row = g_lst[e * T_TOK + i0 + j];
                int t = row >> 1;
                if (v == 0) sr[j] = row;
                s1[j][v] = LSCALE * g_lrall[t * 256 + e * RNK + v];
                s3[j][v] = LSCALE * g_lrall[t * 256 + 128 + e * RNK + v];
            }
        }
        __syncthreads();
        int jj = 0;
        for (; jj + 2 <= batch; jj += 2) {
            int rowA = sr[jj], rowB = sr[jj + 1];
            int tA = rowA >> 1, tB = rowB >> 1;
            float h1a = __half2float(g_b1h[(size_t)tA * FDIM + f]);
            float h3a = __half2float(g_b3h[(size_t)tA * FDIM + f]);
            float h1b = __half2float(g_b1h[(size_t)tB * FDIM + f]);
            float h3b = __half2float(g_b3h[(size_t)tB * FDIM + f]);
#pragma unroll
            for (int r = 0; r < RNK; r++) {
                h1a = fmaf(s1[jj][r], br1[r], h1a);
                h3a = fmaf(s3[jj][r], br3[r], h3a);
                h1b = fmaf(s1[jj + 1][r], br1[r], h1b);
                h3b = fmaf(s3[jj + 1][r], br3[r], h3b);
            }
            g_acth[(size_t)rowA * FDIM + f] = __float2half(fast_silu(h1a) * h3a);
            g_acth[(size_t)rowB * FDIM + f] = __float2half(fast_silu(h1b) * h3b);
        }
        if (jj < batch) {
            int row = sr[jj];
            int t = row >> 1;
            float h1 = __half2float(g_b1h[(size_t)t * FDIM + f]);
            float h3 = __half2float(g_b3h[(size_t)t * FDIM + f]);
#pragma unroll
            for (int r = 0; r < RNK; r++) {
                h1 = fmaf(s1[jj][r], br1[r], h1);
                h3 = fmaf(s3[jj][r], br3[r], h3);
            }
            g_acth[(size_t)row * FDIM + f] = __float2half(fast_silu(h1) * h3);
        }
    }
}

// ---------------- K6: expert-grouped LoRA-A down proj, F-split x8 -----------
#define L2FC 512
#define L2ST 516
__global__ void __launch_bounds__(256)
k_lora2g(const float* __restrict__ a2) {
    extern __shared__ float smf[];
    float* s_act = smf;                  // [32][516]
    float* s_a2  = smf + 32 * L2ST;      // [16][516]
    int e = blockIdx.x, rb = blockIdx.y, bz = blockIdx.z;
    int n = g_cnt[e];
    int r0 = rb * 32;
    if (r0 >= n) return;
    int nrows = min(32, n - r0);
    int tid = threadIdx.x;
    __shared__ int s_row[32];
    if (tid < 32) s_row[tid] = (tid < nrows) ? g_lst[e * T_TOK + r0 + tid] : -1;
    __syncthreads();
    int myrow = tid >> 3;
    int rp = (tid & 7) * 2;
    float acc0 = 0.f, acc1 = 0.f;
    int f0 = bz * L2FC;
    {
        for (int q = tid; q < 32 * 64; q += 256) {
            int j = q >> 6, c = q & 63;
            float* d = s_act + j * L2ST + c * 8;
            int row = s_row[j];
            if (row >= 0) {
                uint4 v = *(const uint4*)(g_acth + (size_t)row * FDIM + f0 + c * 8);
                __half2 h0 = *(__half2*)&v.x, h1 = *(__half2*)&v.y;
                __half2 h2 = *(__half2*)&v.z, h3 = *(__half2*)&v.w;
                float2 f0v = __half22float2(h0), f1v = __half22float2(h1);
                float2 f2v = __half22float2(h2), f3v = __half22float2(h3);
                d[0] = f0v.x; d[1] = f0v.y; d[2] = f1v.x; d[3] = f1v.y;
                d[4] = f2v.x; d[5] = f2v.y; d[6] = f3v.x; d[7] = f3v.y;
            } else {
                for (int z = 0; z < 8; z++) d[z] = 0.f;
            }
        }
        for (int q = tid; q < 16 * 128; q += 256) {
            int j = q >> 7, c4 = q & 127;
            float4 v = *(const float4*)(a2 + ((size_t)e * RNK + j) * FDIM + f0 + c4 * 4);
            float* d = s_a2 + j * L2ST + c4 * 4;
            d[0] = v.x; d[1] = v.y; d[2] = v.z; d[3] = v.w;
        }
        __syncthreads();
        const float* ar0 = s_a2 + rp * L2ST;
        const float* ar1 = s_a2 + (rp + 1) * L2ST;
        const float* ac = s_act + myrow * L2ST;
#pragma unroll 8
        for (int f = 0; f < L2FC; f++) {
            float a = ac[f];
            acc0 = fmaf(a, ar0[f], acc0);
            acc1 = fmaf(a, ar1[f], acc1);
        }
    }
    if (myrow < nrows) {
        int row = s_row[myrow];
        g_lr2p[bz][row * RNK + rp]     = LSCALE * acc0;
        g_lr2p[bz][row * RNK + rp + 1] = LSCALE * acc1;
    }
}

// ---------------- K8: LoRA-B down + expert mix (sums partials) --------------
__global__ void k_mix(const float* __restrict__ b2, float* __restrict__ out) {
    int t = blockIdx.x;
    __shared__ float l2[TOPK][RNK];
    __shared__ int   se[TOPK];
    __shared__ float sw[TOPK];
    if (threadIdx.x < TOPK * RNK) {
        int k = threadIdx.x / RNK, r = threadIdx.x % RNK;
        int off = (t * TOPK + k) * RNK + r;
        float s = 0.f;
#pragma unroll
        for (int z = 0; z < 8; z++) s += g_lr2p[z][off];
        l2[k][r] = s;
    }
    if (threadIdx.x < TOPK) {
        se[threadIdx.x] = g_idx[t * TOPK + threadIdx.x];
        sw[threadIdx.x] = g_wgt[t * TOPK + threadIdx.x];
    }
    __syncthreads();
    for (int d = threadIdx.x; d < DDIM; d += blockDim.x) {
        float o = 0.f;
#pragma unroll
        for (int k = 0; k < TOPK; k++) {
            size_t off = (size_t)(t * TOPK + k) * DDIM + d;
            float v = g_yp[0][off] + g_yp[1][off] + g_yp[2][off] + g_yp[3][off];
            const float4* br = (const float4*)(b2 + ((size_t)se[k] * DDIM + d) * RNK);
#pragma unroll
            for (int q = 0; q < 4; q++) {
                float4 b = br[q];
                v += l2[k][q*4+0]*b.x + l2[k][q*4+1]*b.y + l2[k][q*4+2]*b.z + l2[k][q*4+3]*b.w;
            }
            o += sw[k] * v;
        }
        out[t * DDIM + d] = o;
    }
}

// ---------------- launch ----------------------------------------------------
extern "C" void kernel_launch(void* const* d_in, const int* in_sizes, int n_in,
                              void* d_out, int out_size) {
    const float* x      = (const float*)d_in[0];
    const float* norm_w = (const float*)d_in[1];
    const float* w1     = (const float*)d_in[2];
    const float* w3     = (const float*)d_in[3];
    const float* w2     = (const float*)d_in[4];
    const float* gate_w = (const float*)d_in[5];
    const float* a1     = (const float*)d_in[6];
    const float* b1     = (const float*)d_in[7];
    const float* a3     = (const float*)d_in[8];
    const float* b3     = (const float*)d_in[9];
    const float* a2     = (const float*)d_in[10];
    const float* b2     = (const float*)d_in[11];
    float* out = (float*)d_out;

    cudaFuncSetAttribute(k_lora2g, cudaFuncAttributeMaxDynamicSharedMemorySize,
                         48 * L2ST * 4);
    cudaFuncSetAttribute(k_up_gemm, cudaFuncAttributeMaxDynamicSharedMemorySize, GSM);
    cudaFuncSetAttribute(k_dn_gemm, cudaFuncAttributeMaxDynamicSharedMemorySize, GSM);

    // total float4 count: 2M (w1,w3) + 1M (w2) + 64K (a1,a3)
    const int cvt_blocks = (2 * 1048576 + 1048576 + 2 * 32768) / 256;

    k_cvt_all<<<cvt_blocks, 256>>>(w1, w3, w2, a1, a3);       // 1
    k_rmsnorm_rt<<<T_TOK, 256>>>(x, norm_w, gate_w);          // 2
    k_build<<<1, T_TOK * TOPK>>>();                           // 3
    k_up_gemm<<<dim3(66, 4), 256, GSM>>>();                   // 4  <- profiled
    k_act2<<<dim3(NEXP, FDIM / 256, 4), 256>>>(b1, b3);       // 5
    k_lora2g<<<dim3(NEXP, 16, 8), 256, 48 * L2ST * 4>>>(a2);  // 6
    k_dn_gemm<<<dim3(8, 8, 4), 256, GSM>>>();                 // 7
    k_mix<<<T_TOK, 256>>>(b2, out);                           // 8
}